// round 15
// baseline (speedup 1.0000x reference)
#include <cuda_runtime.h>
#include <cuda_fp16.h>
#include <math.h>
#include <stdint.h>

#define D_IN 128
#define H1 256
#define H2 128
#define NMAX 150016
#define BMAX 16384
#define EMAX 4800000

// ---------------- scratch (device globals; no runtime alloc) ----------------
__device__ __half g_y1h[(size_t)NMAX * D_IN];    // fp16 A@x
__device__ __half g_agg1h[(size_t)NMAX * H1];    // fp16 (A@x)@W1 + s b1
__device__ __half g_embh[(size_t)NMAX * D_IN];   // fp16 copy of [uemb;iemb]
__device__ __half g_t2h[(size_t)NMAX * H2];      // fp16 t2 (written by gemm2)
__device__ __half g_y2h[(size_t)NMAX * H2];      // fp16 A@t2
__device__ float g_s[NMAX];
__device__ float g_sum1[H1], g_sq1[H1], g_scale1[H1], g_shift1[H1];
__device__ float g_sum2[H2], g_sq2[H2], g_scale2[H2], g_shift2[H2];
__device__ int g_cnt[NMAX];
__device__ int g_offs[NMAX + 1];
__device__ int g_offs_tmp[NMAX];
__device__ int2 g_csr[EMAX];

static inline int cdiv(int a, int b) { return (a + b - 1) / b; }

// ---------------- numeric helpers ----------------
__device__ __forceinline__ unsigned f2tf32(float x) {
    unsigned r;
    asm("cvt.rna.tf32.f32 %0, %1;" : "=r"(r) : "f"(x));
    return r;
}
__device__ __forceinline__ void mma_tf32(float* c, const unsigned* a, const unsigned* b) {
    asm volatile(
        "mma.sync.aligned.m16n8k8.row.col.f32.tf32.tf32.f32 "
        "{%0,%1,%2,%3}, {%4,%5,%6,%7}, {%8,%9}, {%0,%1,%2,%3};"
        : "+f"(c[0]), "+f"(c[1]), "+f"(c[2]), "+f"(c[3])
        : "r"(a[0]), "r"(a[1]), "r"(a[2]), "r"(a[3]), "r"(b[0]), "r"(b[1]));
}

// ---------------- merged: edge counting + fp16 embedding conversion ----------------
__global__ void count_conv(const int* __restrict__ rows, int E, int cblocks,
                           const float* __restrict__ uemb, const float* __restrict__ iemb,
                           int n_users, int N) {
    if ((int)blockIdx.x < cblocks) {
        int i = blockIdx.x * 256 + threadIdx.x;
        if (i < E) atomicAdd(&g_cnt[__ldg(rows + i)], 1);
    } else {
        long long i = (long long)(blockIdx.x - cblocks) * 256 + threadIdx.x;
        long long total = (long long)N * (D_IN / 4);
        if (i >= total) return;
        int node = (int)(i >> 5);
        int q = (int)(i & 31);
        const float* src = (node < n_users) ? (uemb + (size_t)node * D_IN)
                                            : (iemb + (size_t)(node - n_users) * D_IN);
        float4 v = __ldg((const float4*)src + q);
        __half2 h0 = __floats2half2_rn(v.x, v.y);
        __half2 h1 = __floats2half2_rn(v.z, v.w);
        *(uint2*)(g_embh + (size_t)node * D_IN + q * 4) =
            make_uint2(*(unsigned*)&h0, *(unsigned*)&h1);
    }
}

__global__ void __launch_bounds__(1024) scan_offsets(int N) {
    __shared__ int sums[1024];
    int t = threadIdx.x;
    int chunk = (N + 1023) / 1024;
    int lo = t * chunk;
    int hi = min(lo + chunk, N);
    int s = 0;
    for (int i = lo; i < hi; i++) s += g_cnt[i];
    sums[t] = s;
    __syncthreads();
    for (int off = 1; off < 1024; off <<= 1) {
        int add = (t >= off) ? sums[t - off] : 0;
        int v = sums[t];
        __syncthreads();
        sums[t] = v + add;
        __syncthreads();
    }
    int run = (t == 0) ? 0 : sums[t - 1];
    for (int i = lo; i < hi; i++) {
        g_offs[i] = run;
        g_offs_tmp[i] = run;
        run += g_cnt[i];
    }
    if (t == 1023) g_offs[N] = sums[1023];
}

__global__ void fill_csr(const int* __restrict__ rows, const int* __restrict__ cols,
                         const float* __restrict__ vals, int E) {
    int i = blockIdx.x * blockDim.x + threadIdx.x;
    if (i >= E) return;
    int r = __ldg(rows + i);
    int pos = atomicAdd(&g_offs_tmp[r], 1);
    g_csr[pos] = make_int2(__ldg(cols + i), __float_as_int(__ldg(vals + i)));
}

// ---------------- layer-1 aggregation (fp16 gather, fp32 accumulate, fp16 out) ----------------
__global__ void agg_emb(int N) {
    int row = (blockIdx.x * blockDim.x + threadIdx.x) >> 5;
    int lane = threadIdx.x & 31;
    if (row >= N) return;
    int start = g_offs[row];
    int end = g_offs[row + 1];
    float4 acc = make_float4(0.f, 0.f, 0.f, 0.f);
    float sv = 0.f;
#pragma unroll 4
    for (int i = start; i < end; i++) {
        int2 cv = __ldg(&g_csr[i]);
        float v = __int_as_float(cv.y);
        uint2 h = __ldg(((const uint2*)(g_embh + (size_t)cv.x * D_IN)) + lane);
        float2 f0 = __half22float2(*(__half2*)&h.x);
        float2 f1 = __half22float2(*(__half2*)&h.y);
        acc.x = fmaf(v, f0.x, acc.x);
        acc.y = fmaf(v, f0.y, acc.y);
        acc.z = fmaf(v, f1.x, acc.z);
        acc.w = fmaf(v, f1.y, acc.w);
        sv += v;
    }
    __half2 o0 = __floats2half2_rn(acc.x, acc.y);
    __half2 o1 = __floats2half2_rn(acc.z, acc.w);
    *(uint2*)(g_y1h + (size_t)row * D_IN + lane * 4) =
        make_uint2(*(unsigned*)&o0, *(unsigned*)&o1);
    if (lane == 0) g_s[row] = sv;
}

// ---------------- layer-2 aggregation (fp16 gather, fp16 out) + fused column stats ----------------
__global__ void agg_dense_stats(int N) {
    __shared__ float s_sum[H2], s_sq[H2];
    int tid = threadIdx.x;
    if (tid < H2) {
        s_sum[tid] = 0.f;
        s_sq[tid] = 0.f;
    }
    __syncthreads();

    int row = (blockIdx.x * blockDim.x + tid) >> 5;
    int lane = tid & 31;
    if (row < N) {
        int start = g_offs[row];
        int end = g_offs[row + 1];
        float4 acc = make_float4(0.f, 0.f, 0.f, 0.f);
#pragma unroll 4
        for (int i = start; i < end; i++) {
            int2 cv = __ldg(&g_csr[i]);
            float v = __int_as_float(cv.y);
            uint2 h = __ldg(((const uint2*)(g_t2h + (size_t)cv.x * H2)) + lane);
            float2 f0 = __half22float2(*(__half2*)&h.x);
            float2 f1 = __half22float2(*(__half2*)&h.y);
            acc.x = fmaf(v, f0.x, acc.x);
            acc.y = fmaf(v, f0.y, acc.y);
            acc.z = fmaf(v, f1.x, acc.z);
            acc.w = fmaf(v, f1.y, acc.w);
        }
        __half2 o0 = __floats2half2_rn(acc.x, acc.y);
        __half2 o1 = __floats2half2_rn(acc.z, acc.w);
        *(uint2*)(g_y2h + (size_t)row * H2 + lane * 4) =
            make_uint2(*(unsigned*)&o0, *(unsigned*)&o1);
        atomicAdd(&s_sum[lane * 4 + 0], acc.x);
        atomicAdd(&s_sum[lane * 4 + 1], acc.y);
        atomicAdd(&s_sum[lane * 4 + 2], acc.z);
        atomicAdd(&s_sum[lane * 4 + 3], acc.w);
        atomicAdd(&s_sq[lane * 4 + 0], acc.x * acc.x);
        atomicAdd(&s_sq[lane * 4 + 1], acc.y * acc.y);
        atomicAdd(&s_sq[lane * 4 + 2], acc.z * acc.z);
        atomicAdd(&s_sq[lane * 4 + 3], acc.w * acc.w);
    }
    __syncthreads();
    if (tid < H2) {
        atomicAdd(&g_sum2[tid], s_sum[tid]);
        atomicAdd(&g_sq2[tid], s_sq[tid]);
    }
}

// ---------------- layer-1 column stats (fp16 input, vectorized 8 halves/thread) ----------------
__global__ void colstats_h8(const __half* __restrict__ X, int M, int C,
                            float* __restrict__ osum, float* __restrict__ osq) {
    int ngrp = C / 8;                 // 32 col-groups for C=256
    int cg = threadIdx.x % ngrp;      // col-group
    int sub = threadIdx.x / ngrp;     // row substripe within block
    int nsub = blockDim.x / ngrp;     // 8
    float s[8] = {}, q[8] = {};
    for (int r = blockIdx.x * nsub + sub; r < M; r += gridDim.x * nsub) {
        uint4 hv = __ldg((const uint4*)(X + (size_t)r * C + cg * 8));
        const unsigned* hw = &hv.x;
#pragma unroll
        for (int j = 0; j < 4; j++) {
            float2 f = __half22float2(*(__half2*)&hw[j]);
            s[2 * j] += f.x;
            q[2 * j] += f.x * f.x;
            s[2 * j + 1] += f.y;
            q[2 * j + 1] += f.y * f.y;
        }
    }
#pragma unroll
    for (int j = 0; j < 8; j++) {
        atomicAdd(&osum[cg * 8 + j], s[j]);
        atomicAdd(&osq[cg * 8 + j], q[j]);
    }
}

__global__ void bn_fin(const float* __restrict__ isum, const float* __restrict__ isq,
                       const float* __restrict__ g, const float* __restrict__ beta,
                       float invM, int C, float* __restrict__ oscale, float* __restrict__ oshift) {
    int c = threadIdx.x;
    if (c < C) {
        float mu = isum[c] * invM;
        float var = isq[c] * invM - mu * mu;
        float rs = rsqrtf(var + 1e-5f);
        float sc = rs * g[c];
        oscale[c] = sc;
        oshift[c] = beta[c] - mu * sc;
    }
}

// ---------------- TF32 tensor-core GEMM: 128x128x16 CTA, 8 warps (32x64 each) ----------------
// INH: A is fp16.  OUTH: write fp16 C.
template <bool INH, bool TRANSA, bool SROWBIAS, bool OUTH>
__global__ void __launch_bounds__(256) gemm_tc(
    const void* __restrict__ A, const float* __restrict__ Bw, void* __restrict__ Cout,
    int M, int Nn, int Kk,
    const float* __restrict__ bias, const float* __restrict__ srow,
    const float* __restrict__ tscale, const float* __restrict__ tshift) {
    const int BM = 128, BN = 128, BK = 16;
    __shared__ unsigned As[2][BM][BK + 4];   // [m][k]
    __shared__ unsigned Bs[2][BK][BN + 4];   // [k][n]
    __shared__ float s_sc[256], s_sh[256];

    int tid = threadIdx.x;
    int lane = tid & 31;
    int w = tid >> 5;
    int m0 = blockIdx.x * BM;
    int n0 = blockIdx.y * BN;
    int warp_m = (w & 3) * 32;
    int warp_n = (w >> 2) * 64;

    if (TRANSA) {
        for (int k = tid; k < Kk; k += 256) {
            s_sc[k] = tscale[k];
            s_sh[k] = tshift[k];
        }
        __syncthreads();
    }

    float acc[2][8][4];
#pragma unroll
    for (int mf = 0; mf < 2; mf++)
#pragma unroll
        for (int nf = 0; nf < 8; nf++)
#pragma unroll
            for (int c = 0; c < 4; c++) acc[mf][nf][c] = 0.f;

    int T = Kk / BK;
    float4 ra[2], rb[2];

#define G_LOAD(t)                                                                     \
    {                                                                                 \
        int k0 = (t) * BK;                                                            \
        _Pragma("unroll") for (int r = 0; r < 2; r++) {                               \
            int f = tid + r * 256;                                                    \
            int row = f >> 2, colq = f & 3;                                           \
            ra[r] = make_float4(0.f, 0.f, 0.f, 0.f);                                  \
            if (m0 + row < M) {                                                       \
                if (INH) {                                                            \
                    uint2 hv = __ldg((const uint2*)((const __half*)A +                \
                                     (size_t)(m0 + row) * Kk + k0 + colq * 4));       \
                    float2 a0 = __half22float2(*(__half2*)&hv.x);                     \
                    float2 a1 = __half22float2(*(__half2*)&hv.y);                     \
                    ra[r] = make_float4(a0.x, a0.y, a1.x, a1.y);                      \
                } else {                                                              \
                    ra[r] = __ldg((const float4*)((const float*)A +                   \
                                  (size_t)(m0 + row) * Kk + k0 + colq * 4));          \
                }                                                                     \
            }                                                                         \
        }                                                                             \
        _Pragma("unroll") for (int r = 0; r < 2; r++) {                               \
            int f = tid + r * 256;                                                    \
            int row = f >> 5, colq = f & 31;                                          \
            rb[r] = __ldg((const float4*)(Bw + (size_t)(k0 + row) * Nn + n0 + colq * 4)); \
        }                                                                             \
    }

#define S_STORE(buf, t)                                                               \
    {                                                                                 \
        int k0 = (t) * BK;                                                            \
        _Pragma("unroll") for (int r = 0; r < 2; r++) {                               \
            int f = tid + r * 256;                                                    \
            int row = f >> 2, colq = f & 3;                                           \
            float vx = ra[r].x, vy = ra[r].y, vz = ra[r].z, vw = ra[r].w;             \
            if (TRANSA) {                                                             \
                int gk = k0 + colq * 4;                                               \
                vx = fmaxf(0.f, fmaf(vx, s_sc[gk + 0], s_sh[gk + 0]));                \
                vy = fmaxf(0.f, fmaf(vy, s_sc[gk + 1], s_sh[gk + 1]));                \
                vz = fmaxf(0.f, fmaf(vz, s_sc[gk + 2], s_sh[gk + 2]));                \
                vw = fmaxf(0.f, fmaf(vw, s_sc[gk + 3], s_sh[gk + 3]));                \
            }                                                                         \
            uint4 p = make_uint4(f2tf32(vx), f2tf32(vy), f2tf32(vz), f2tf32(vw));     \
            *(uint4*)&As[buf][row][colq * 4] = p;                                     \
        }                                                                             \
        _Pragma("unroll") for (int r = 0; r < 2; r++) {                               \
            int f = tid + r * 256;                                                    \
            int row = f >> 5, colq = f & 31;                                          \
            uint4 p = make_uint4(f2tf32(rb[r].x), f2tf32(rb[r].y), f2tf32(rb[r].z),   \
                                 f2tf32(rb[r].w));                                    \
            *(uint4*)&Bs[buf][row][colq * 4] = p;                                     \
        }                                                                             \
    }

    G_LOAD(0)
    S_STORE(0, 0)
    __syncthreads();

    for (int t = 0; t < T; t++) {
        int cur = t & 1;
        if (t + 1 < T) G_LOAD(t + 1)
#pragma unroll
        for (int ks = 0; ks < 2; ks++) {
            int k0 = ks * 8;
            unsigned afr[2][4], bfr[8][2];
            int arow = warp_m + (lane >> 2);
            int akc = k0 + (lane & 3);
#pragma unroll
            for (int mf = 0; mf < 2; mf++) {
                int r = arow + mf * 16;
                afr[mf][0] = As[cur][r][akc];
                afr[mf][1] = As[cur][r + 8][akc];
                afr[mf][2] = As[cur][r][akc + 4];
                afr[mf][3] = As[cur][r + 8][akc + 4];
            }
            int bcol = warp_n + (lane >> 2);
            int bkr = k0 + (lane & 3);
#pragma unroll
            for (int nf = 0; nf < 8; nf++) {
                bfr[nf][0] = Bs[cur][bkr][bcol + nf * 8];
                bfr[nf][1] = Bs[cur][bkr + 4][bcol + nf * 8];
            }
#pragma unroll
            for (int mf = 0; mf < 2; mf++)
#pragma unroll
                for (int nf = 0; nf < 8; nf++) mma_tf32(acc[mf][nf], afr[mf], bfr[nf]);
        }
        if (t + 1 < T) {
            S_STORE((t + 1) & 1, t + 1)
            __syncthreads();
        }
    }

    // epilogue
#pragma unroll
    for (int mf = 0; mf < 2; mf++) {
        int r0 = m0 + warp_m + mf * 16 + (lane >> 2);
#pragma unroll
        for (int half = 0; half < 2; half++) {
            int gr = r0 + half * 8;
            if (gr >= M) continue;
            float sv = 1.0f;
            if (SROWBIAS) sv = __ldg(srow + gr);
#pragma unroll
            for (int nf = 0; nf < 8; nf++) {
                int gc = n0 + warp_n + nf * 8 + 2 * (lane & 3);
                float v0 = acc[mf][nf][half * 2 + 0] + sv * __ldg(bias + gc);
                float v1 = acc[mf][nf][half * 2 + 1] + sv * __ldg(bias + gc + 1);
                if (OUTH) {
                    __half2 hv = __floats2half2_rn(v0, v1);
                    *(unsigned*)((__half*)Cout + (size_t)gr * Nn + gc) = *(unsigned*)&hv;
                } else {
                    *(float2*)((float*)Cout + (size_t)gr * Nn + gc) = make_float2(v0, v1);
                }
            }
        }
    }
#undef G_LOAD
#undef S_STORE
}

// ---------------- fused head: gather(BN2+relu, fp16 y2) -> GEMM(P1,relu) -> dot(P2) ----------------
__global__ void __launch_bounds__(256) head_fused(
    const int* __restrict__ uidx, const int* __restrict__ iidx, int n_users, int B,
    const float* __restrict__ P1, const float* __restrict__ pb1,
    const float* __restrict__ P2, const float* __restrict__ pb2,
    float* __restrict__ out) {
    const int BK = 16, T = 256 / BK;
    __shared__ unsigned As[2][128][BK + 4];
    __shared__ unsigned Bs[2][BK][128 + 8];
    __shared__ float s_sc[H2], s_sh[H2], s_pb1[H2], s_p2[H2], s_hs[128];

    int tid = threadIdx.x;
    int lane = tid & 31;
    int w = tid >> 5;
    int m0 = blockIdx.x * 128;
    int warp_m = (w & 3) * 32;
    int warp_n = (w >> 2) * 64;

    if (tid < H2) {
        s_sc[tid] = g_scale2[tid];
        s_sh[tid] = g_shift2[tid];
        s_pb1[tid] = __ldg(pb1 + tid);
        s_p2[tid] = __ldg(P2 + tid);
    }
    if (tid < 128) s_hs[tid] = 0.f;
    __syncthreads();

    int arow = tid >> 1;
    int acol = (tid & 1) * 8;
    int gb = m0 + arow;
    bool brow_ok = gb < B;
    int node_u = brow_ok ? __ldg(uidx + gb) : 0;
    int node_i = brow_ok ? (n_users + __ldg(iidx + gb)) : 0;

    float acc[2][8][4];
#pragma unroll
    for (int mf = 0; mf < 2; mf++)
#pragma unroll
        for (int nf = 0; nf < 8; nf++)
#pragma unroll
            for (int c = 0; c < 4; c++) acc[mf][nf][c] = 0.f;

    float4 ra[2], rb[2];

#define HG_LOAD(t)                                                                    \
    {                                                                                 \
        int gk = (t) * BK + acol;                                                     \
        int nd = (gk < 128) ? node_u : node_i;                                        \
        int c = gk & 127;                                                             \
        ra[0] = make_float4(0.f, 0.f, 0.f, 0.f);                                      \
        ra[1] = make_float4(0.f, 0.f, 0.f, 0.f);                                      \
        if (brow_ok) {                                                                \
            uint4 hv = __ldg((const uint4*)(g_y2h + (size_t)nd * H2 + c));            \
            float2 a0 = __half22float2(*(__half2*)&hv.x);                             \
            float2 a1 = __half22float2(*(__half2*)&hv.y);                             \
            float2 a2 = __half22float2(*(__half2*)&hv.z);                             \
            float2 a3 = __half22float2(*(__half2*)&hv.w);                             \
            ra[0] = make_float4(a0.x, a0.y, a1.x, a1.y);                              \
            ra[1] = make_float4(a2.x, a2.y, a3.x, a3.y);                              \
        }                                                                             \
        _Pragma("unroll") for (int r = 0; r < 2; r++) {                               \
            int f = tid + r * 256;                                                    \
            int row = f >> 5, colq = f & 31;                                          \
            rb[r] = __ldg((const float4*)(P1 + (size_t)((t) * BK + row) * H2 + colq * 4)); \
        }                                                                             \
    }

#define HS_STORE(buf, t)                                                              \
    {                                                                                 \
        int gk = (t) * BK + acol;                                                     \
        int c = gk & 127;                                                             \
        _Pragma("unroll") for (int h = 0; h < 2; h++) {                               \
            float4 v = ra[h];                                                         \
            int cc = c + h * 4;                                                       \
            v.x = fmaxf(0.f, fmaf(v.x, s_sc[cc + 0], s_sh[cc + 0]));                  \
            v.y = fmaxf(0.f, fmaf(v.y, s_sc[cc + 1], s_sh[cc + 1]));                  \
            v.z = fmaxf(0.f, fmaf(v.z, s_sc[cc + 2], s_sh[cc + 2]));                  \
            v.w = fmaxf(0.f, fmaf(v.w, s_sc[cc + 3], s_sh[cc + 3]));                  \
            uint4 p = make_uint4(f2tf32(v.x), f2tf32(v.y), f2tf32(v.z), f2tf32(v.w)); \
            *(uint4*)&As[buf][arow][acol + h * 4] = p;                                \
        }                                                                             \
        _Pragma("unroll") for (int r = 0; r < 2; r++) {                               \
            int f = tid + r * 256;                                                    \
            int row = f >> 5, colq = f & 31;                                          \
            uint4 p = make_uint4(f2tf32(rb[r].x), f2tf32(rb[r].y), f2tf32(rb[r].z),   \
                                 f2tf32(rb[r].w));                                    \
            *(uint4*)&Bs[buf][row][colq * 4] = p;                                     \
        }                                                                             \
    }

    HG_LOAD(0)
    HS_STORE(0, 0)
    __syncthreads();

    for (int t = 0; t < T; t++) {
        int cur = t & 1;
        if (t + 1 < T) HG_LOAD(t + 1)
#pragma unroll
        for (int ks = 0; ks < 2; ks++) {
            int k0 = ks * 8;
            unsigned afr[2][4], bfr[8][2];
            int arw = warp_m + (lane >> 2);
            int akc = k0 + (lane & 3);
#pragma unroll
            for (int mf = 0; mf < 2; mf++) {
                int r = arw + mf * 16;
                afr[mf][0] = As[cur][r][akc];
                afr[mf][1] = As[cur][r + 8][akc];
                afr[mf][2] = As[cur][r][akc + 4];
                afr[mf][3] = As[cur][r + 8][akc + 4];
            }
            int bc = warp_n + (lane >> 2);
            int bkr = k0 + (lane & 3);
#pragma unroll
            for (int nf = 0; nf < 8; nf++) {
                bfr[nf][0] = Bs[cur][bkr][bc + nf * 8];
                bfr[nf][1] = Bs[cur][bkr + 4][bc + nf * 8];
            }
#pragma unroll
            for (int mf = 0; mf < 2; mf++)
#pragma unroll
                for (int nf = 0; nf < 8; nf++) mma_tf32(acc[mf][nf], afr[mf], bfr[nf]);
        }
        if (t + 1 < T) {
            HS_STORE((t + 1) & 1, t + 1)
            __syncthreads();
        }
    }

#pragma unroll
    for (int mf = 0; mf < 2; mf++) {
#pragma unroll
        for (int half = 0; half < 2; half++) {
            int lr = warp_m + mf * 16 + half * 8 + (lane >> 2);
            float part = 0.f;
#pragma unroll
            for (int nf = 0; nf < 8; nf++) {
                int gc = warp_n + nf * 8 + 2 * (lane & 3);
                float v0 = fmaxf(acc[mf][nf][half * 2 + 0] + s_pb1[gc], 0.f);
                float v1 = fmaxf(acc[mf][nf][half * 2 + 1] + s_pb1[gc + 1], 0.f);
                part = fmaf(v0, s_p2[gc], part);
                part = fmaf(v1, s_p2[gc + 1], part);
            }
            atomicAdd(&s_hs[lr], part);
        }
    }
    __syncthreads();
    if (tid < 128 && m0 + tid < B) out[m0 + tid] = s_hs[tid] + __ldg(pb2);
#undef HG_LOAD
#undef HS_STORE
}

// ---------------- launch ----------------
extern "C" void kernel_launch(void* const* d_in, const int* in_sizes, int n_in,
                              void* d_out, int out_size) {
    const int* uidx = (const int*)d_in[0];
    const int* iidx = (const int*)d_in[1];
    const int* erow = (const int*)d_in[2];
    const int* ecol = (const int*)d_in[3];
    const float* eval = (const float*)d_in[4];
    const float* uemb = (const float*)d_in[5];
    const float* iemb = (const float*)d_in[6];
    const float* W1 = (const float*)d_in[7];
    const float* b1 = (const float*)d_in[8];
    const float* g1 = (const float*)d_in[9];
    const float* beta1 = (const float*)d_in[10];
    const float* W2 = (const float*)d_in[11];
    const float* b2 = (const float*)d_in[12];
    const float* g2 = (const float*)d_in[13];
    const float* beta2 = (const float*)d_in[14];
    const float* P1 = (const float*)d_in[15];
    const float* pb1 = (const float*)d_in[16];
    const float* P2 = (const float*)d_in[17];
    const float* pb2 = (const float*)d_in[18];
    float* out = (float*)d_out;

    int B = in_sizes[0];
    int E = in_sizes[2];
    int n_users = in_sizes[5] / D_IN;
    int n_items = in_sizes[6] / D_IN;
    int N = n_users + n_items;

    void *y1hp, *agg1hp, *t2hp, *sp;
    void *sum1p, *sq1p, *scale1p, *shift1p, *sum2p, *sq2p, *scale2p, *shift2p;
    void *cntp;
    cudaGetSymbolAddress(&y1hp, g_y1h);
    cudaGetSymbolAddress(&agg1hp, g_agg1h);
    cudaGetSymbolAddress(&t2hp, g_t2h);
    cudaGetSymbolAddress(&sp, g_s);
    cudaGetSymbolAddress(&sum1p, g_sum1);
    cudaGetSymbolAddress(&sq1p, g_sq1);
    cudaGetSymbolAddress(&scale1p, g_scale1);
    cudaGetSymbolAddress(&shift1p, g_shift1);
    cudaGetSymbolAddress(&sum2p, g_sum2);
    cudaGetSymbolAddress(&sq2p, g_sq2);
    cudaGetSymbolAddress(&scale2p, g_scale2);
    cudaGetSymbolAddress(&shift2p, g_shift2);
    cudaGetSymbolAddress(&cntp, g_cnt);

    cudaMemsetAsync(cntp, 0, (size_t)N * sizeof(int));
    cudaMemsetAsync(sum1p, 0, H1 * sizeof(float));
    cudaMemsetAsync(sq1p, 0, H1 * sizeof(float));
    cudaMemsetAsync(sum2p, 0, H2 * sizeof(float));
    cudaMemsetAsync(sq2p, 0, H2 * sizeof(float));

    // ----- CSR build + fp16 embedding table (merged count+conv grid) -----
    int cblocks = cdiv(E, 256);
    int vblocks = cdiv(N * 32, 256);
    count_conv<<<cblocks + vblocks, 256>>>(erow, E, cblocks, uemb, iemb, n_users, N);
    scan_offsets<<<1, 1024>>>(N);
    fill_csr<<<cdiv(E, 256), 256>>>(erow, ecol, eval, E);

    // ----- Layer 1: aggregate (fp16) then transform to h1=256 (fp16 in/out) -----
    agg_emb<<<cdiv(N, 8), 256>>>(N);
    gemm_tc<true, false, true, true><<<dim3(cdiv(N, 128), H1 / 128), 256>>>(
        y1hp, W1, agg1hp, N, H1, D_IN, b1, (const float*)sp, nullptr, nullptr);
    colstats_h8<<<1024, 256>>>((const __half*)agg1hp, N, H1, (float*)sum1p, (float*)sq1p);
    bn_fin<<<1, 256>>>((const float*)sum1p, (const float*)sq1p, g1, beta1, 1.0f / N, H1,
                       (float*)scale1p, (float*)shift1p);

    // ----- Layer 2: transform (256->128, fp16 in/out) then aggregate (+stats) -----
    gemm_tc<true, true, false, true><<<dim3(cdiv(N, 128), H2 / 128), 256>>>(
        agg1hp, W2, t2hp, N, H2, H1, b2, nullptr, (const float*)scale1p,
        (const float*)shift1p);
    agg_dense_stats<<<cdiv(N, 8), 256>>>(N);
    bn_fin<<<1, 256>>>((const float*)sum2p, (const float*)sq2p, g2, beta2, 1.0f / N, H2,
                       (float*)scale2p, (float*)shift2p);

    // ----- Prediction head (fully fused) -----
    head_fused<<<cdiv(B, 128), 256>>>(uidx, iidx, n_users, B, P1, pb1, P2, pb2, out);
}

// round 16
// speedup vs baseline: 1.0008x; 1.0008x over previous
#include <cuda_runtime.h>
#include <cuda_fp16.h>
#include <math.h>
#include <stdint.h>

#define D_IN 128
#define H1 256
#define H2 128
#define NMAX 150016
#define BMAX 16384
#define EMAX 4800000

// ---------------- scratch (device globals; no runtime alloc) ----------------
__device__ __half g_y1h[(size_t)NMAX * D_IN];    // fp16 A@x
__device__ __half g_agg1h[(size_t)NMAX * H1];    // fp16 (A@x)@W1 + s b1
__device__ __half g_embh[(size_t)NMAX * D_IN];   // fp16 copy of [uemb;iemb]
__device__ __half g_t2h[(size_t)NMAX * H2];      // fp16 t2 (written by gemm2)
__device__ float g_y2[(size_t)NMAX * H2];
__device__ float g_s[NMAX];
__device__ float g_sum1[H1], g_sq1[H1], g_scale1[H1], g_shift1[H1];
__device__ float g_sum2[H2], g_sq2[H2], g_scale2[H2], g_shift2[H2];
__device__ int g_cnt[NMAX];
__device__ int g_offs[NMAX + 1];
__device__ int g_offs_tmp[NMAX];
__device__ int2 g_csr[EMAX];

static inline int cdiv(int a, int b) { return (a + b - 1) / b; }

// ---------------- numeric helpers ----------------
__device__ __forceinline__ unsigned f2tf32(float x) {
    unsigned r;
    asm("cvt.rna.tf32.f32 %0, %1;" : "=r"(r) : "f"(x));
    return r;
}
__device__ __forceinline__ void mma_tf32(float* c, const unsigned* a, const unsigned* b) {
    asm volatile(
        "mma.sync.aligned.m16n8k8.row.col.f32.tf32.tf32.f32 "
        "{%0,%1,%2,%3}, {%4,%5,%6,%7}, {%8,%9}, {%0,%1,%2,%3};"
        : "+f"(c[0]), "+f"(c[1]), "+f"(c[2]), "+f"(c[3])
        : "r"(a[0]), "r"(a[1]), "r"(a[2]), "r"(a[3]), "r"(b[0]), "r"(b[1]));
}

// ---------------- CSR build ----------------
__global__ void count_edges(const int* __restrict__ rows, int E) {
    int i = blockIdx.x * blockDim.x + threadIdx.x;
    if (i < E) atomicAdd(&g_cnt[__ldg(rows + i)], 1);
}

__global__ void __launch_bounds__(1024) scan_offsets(int N) {
    __shared__ int sums[1024];
    int t = threadIdx.x;
    int chunk = (N + 1023) / 1024;
    int lo = t * chunk;
    int hi = min(lo + chunk, N);
    int s = 0;
    for (int i = lo; i < hi; i++) s += g_cnt[i];
    sums[t] = s;
    __syncthreads();
    for (int off = 1; off < 1024; off <<= 1) {
        int add = (t >= off) ? sums[t - off] : 0;
        int v = sums[t];
        __syncthreads();
        sums[t] = v + add;
        __syncthreads();
    }
    int run = (t == 0) ? 0 : sums[t - 1];
    for (int i = lo; i < hi; i++) {
        g_offs[i] = run;
        g_offs_tmp[i] = run;
        run += g_cnt[i];
    }
    if (t == 1023) g_offs[N] = sums[1023];
}

__global__ void fill_csr(const int* __restrict__ rows, const int* __restrict__ cols,
                         const float* __restrict__ vals, int E) {
    int i = blockIdx.x * blockDim.x + threadIdx.x;
    if (i >= E) return;
    int r = __ldg(rows + i);
    int pos = atomicAdd(&g_offs_tmp[r], 1);
    g_csr[pos] = make_int2(__ldg(cols + i), __float_as_int(__ldg(vals + i)));
}

// ---------------- embedding -> fp16 table ----------------
__global__ void conv_emb(const float* __restrict__ uemb, const float* __restrict__ iemb,
                         int n_users, int N) {
    long long i = (long long)blockIdx.x * blockDim.x + threadIdx.x;
    long long total = (long long)N * (D_IN / 4);
    if (i >= total) return;
    int node = (int)(i >> 5);
    int q = (int)(i & 31);
    const float* src = (node < n_users) ? (uemb + (size_t)node * D_IN)
                                        : (iemb + (size_t)(node - n_users) * D_IN);
    float4 v = __ldg((const float4*)src + q);
    __half2 h0 = __floats2half2_rn(v.x, v.y);
    __half2 h1 = __floats2half2_rn(v.z, v.w);
    *(uint2*)(g_embh + (size_t)node * D_IN + q * 4) =
        make_uint2(*(unsigned*)&h0, *(unsigned*)&h1);
}

// ---------------- layer-1 aggregation (fp16 gather, fp32 accumulate, fp16 out) ----------------
__global__ void agg_emb(int N) {
    int row = (blockIdx.x * blockDim.x + threadIdx.x) >> 5;
    int lane = threadIdx.x & 31;
    if (row >= N) return;
    int start = g_offs[row];
    int end = g_offs[row + 1];
    float4 acc = make_float4(0.f, 0.f, 0.f, 0.f);
    float sv = 0.f;
#pragma unroll 4
    for (int i = start; i < end; i++) {
        int2 cv = __ldg(&g_csr[i]);
        float v = __int_as_float(cv.y);
        uint2 h = __ldg(((const uint2*)(g_embh + (size_t)cv.x * D_IN)) + lane);
        float2 f0 = __half22float2(*(__half2*)&h.x);
        float2 f1 = __half22float2(*(__half2*)&h.y);
        acc.x = fmaf(v, f0.x, acc.x);
        acc.y = fmaf(v, f0.y, acc.y);
        acc.z = fmaf(v, f1.x, acc.z);
        acc.w = fmaf(v, f1.y, acc.w);
        sv += v;
    }
    __half2 o0 = __floats2half2_rn(acc.x, acc.y);
    __half2 o1 = __floats2half2_rn(acc.z, acc.w);
    *(uint2*)(g_y1h + (size_t)row * D_IN + lane * 4) =
        make_uint2(*(unsigned*)&o0, *(unsigned*)&o1);
    if (lane == 0) g_s[row] = sv;
}

// ---------------- layer-2 aggregation (fp16 gather) + fused column stats ----------------
__global__ void agg_dense_stats(int N) {
    __shared__ float s_sum[H2], s_sq[H2];
    int tid = threadIdx.x;
    if (tid < H2) {
        s_sum[tid] = 0.f;
        s_sq[tid] = 0.f;
    }
    __syncthreads();

    int row = (blockIdx.x * blockDim.x + tid) >> 5;
    int lane = tid & 31;
    if (row < N) {
        int start = g_offs[row];
        int end = g_offs[row + 1];
        float4 acc = make_float4(0.f, 0.f, 0.f, 0.f);
#pragma unroll 4
        for (int i = start; i < end; i++) {
            int2 cv = __ldg(&g_csr[i]);
            float v = __int_as_float(cv.y);
            uint2 h = __ldg(((const uint2*)(g_t2h + (size_t)cv.x * H2)) + lane);
            float2 f0 = __half22float2(*(__half2*)&h.x);
            float2 f1 = __half22float2(*(__half2*)&h.y);
            acc.x = fmaf(v, f0.x, acc.x);
            acc.y = fmaf(v, f0.y, acc.y);
            acc.z = fmaf(v, f1.x, acc.z);
            acc.w = fmaf(v, f1.y, acc.w);
        }
        *(float4*)(g_y2 + (size_t)row * H2 + lane * 4) = acc;
        atomicAdd(&s_sum[lane * 4 + 0], acc.x);
        atomicAdd(&s_sum[lane * 4 + 1], acc.y);
        atomicAdd(&s_sum[lane * 4 + 2], acc.z);
        atomicAdd(&s_sum[lane * 4 + 3], acc.w);
        atomicAdd(&s_sq[lane * 4 + 0], acc.x * acc.x);
        atomicAdd(&s_sq[lane * 4 + 1], acc.y * acc.y);
        atomicAdd(&s_sq[lane * 4 + 2], acc.z * acc.z);
        atomicAdd(&s_sq[lane * 4 + 3], acc.w * acc.w);
    }
    __syncthreads();
    if (tid < H2) {
        atomicAdd(&g_sum2[tid], s_sum[tid]);
        atomicAdd(&g_sq2[tid], s_sq[tid]);
    }
}

// ---------------- layer-1 column stats (fp16 input, vectorized 8 halves/thread) ----------------
__global__ void colstats_h8(const __half* __restrict__ X, int M, int C,
                            float* __restrict__ osum, float* __restrict__ osq) {
    int ngrp = C / 8;                 // 32 col-groups for C=256
    int cg = threadIdx.x % ngrp;      // col-group
    int sub = threadIdx.x / ngrp;     // row substripe within block
    int nsub = blockDim.x / ngrp;     // 8
    float s[8] = {}, q[8] = {};
    for (int r = blockIdx.x * nsub + sub; r < M; r += gridDim.x * nsub) {
        uint4 hv = __ldg((const uint4*)(X + (size_t)r * C + cg * 8));
        const unsigned* hw = &hv.x;
#pragma unroll
        for (int j = 0; j < 4; j++) {
            float2 f = __half22float2(*(__half2*)&hw[j]);
            s[2 * j] += f.x;
            q[2 * j] += f.x * f.x;
            s[2 * j + 1] += f.y;
            q[2 * j + 1] += f.y * f.y;
        }
    }
#pragma unroll
    for (int j = 0; j < 8; j++) {
        atomicAdd(&osum[cg * 8 + j], s[j]);
        atomicAdd(&osq[cg * 8 + j], q[j]);
    }
}

__global__ void bn_fin(const float* __restrict__ isum, const float* __restrict__ isq,
                       const float* __restrict__ g, const float* __restrict__ beta,
                       float invM, int C, float* __restrict__ oscale, float* __restrict__ oshift) {
    int c = threadIdx.x;
    if (c < C) {
        float mu = isum[c] * invM;
        float var = isq[c] * invM - mu * mu;
        float rs = rsqrtf(var + 1e-5f);
        float sc = rs * g[c];
        oscale[c] = sc;
        oshift[c] = beta[c] - mu * sc;
    }
}

// ---------------- TF32 tensor-core GEMM: 128x128x16 CTA, 8 warps (32x64 each) ----------------
// INH: A is fp16.  OUTH: write fp16 C.
template <bool INH, bool TRANSA, bool SROWBIAS, bool OUTH>
__global__ void __launch_bounds__(256) gemm_tc(
    const void* __restrict__ A, const float* __restrict__ Bw, void* __restrict__ Cout,
    int M, int Nn, int Kk,
    const float* __restrict__ bias, const float* __restrict__ srow,
    const float* __restrict__ tscale, const float* __restrict__ tshift) {
    const int BM = 128, BN = 128, BK = 16;
    __shared__ unsigned As[2][BM][BK + 4];   // [m][k]
    __shared__ unsigned Bs[2][BK][BN + 4];   // [k][n]
    __shared__ float s_sc[256], s_sh[256];

    int tid = threadIdx.x;
    int lane = tid & 31;
    int w = tid >> 5;
    int m0 = blockIdx.x * BM;
    int n0 = blockIdx.y * BN;
    int warp_m = (w & 3) * 32;
    int warp_n = (w >> 2) * 64;

    if (TRANSA) {
        for (int k = tid; k < Kk; k += 256) {
            s_sc[k] = tscale[k];
            s_sh[k] = tshift[k];
        }
        __syncthreads();
    }

    float acc[2][8][4];
#pragma unroll
    for (int mf = 0; mf < 2; mf++)
#pragma unroll
        for (int nf = 0; nf < 8; nf++)
#pragma unroll
            for (int c = 0; c < 4; c++) acc[mf][nf][c] = 0.f;

    int T = Kk / BK;
    float4 ra[2], rb[2];

#define G_LOAD(t)                                                                     \
    {                                                                                 \
        int k0 = (t) * BK;                                                            \
        _Pragma("unroll") for (int r = 0; r < 2; r++) {                               \
            int f = tid + r * 256;                                                    \
            int row = f >> 2, colq = f & 3;                                           \
            ra[r] = make_float4(0.f, 0.f, 0.f, 0.f);                                  \
            if (m0 + row < M) {                                                       \
                if (INH) {                                                            \
                    uint2 hv = __ldg((const uint2*)((const __half*)A +                \
                                     (size_t)(m0 + row) * Kk + k0 + colq * 4));       \
                    float2 a0 = __half22float2(*(__half2*)&hv.x);                     \
                    float2 a1 = __half22float2(*(__half2*)&hv.y);                     \
                    ra[r] = make_float4(a0.x, a0.y, a1.x, a1.y);                      \
                } else {                                                              \
                    ra[r] = __ldg((const float4*)((const float*)A +                   \
                                  (size_t)(m0 + row) * Kk + k0 + colq * 4));          \
                }                                                                     \
            }                                                                         \
        }                                                                             \
        _Pragma("unroll") for (int r = 0; r < 2; r++) {                               \
            int f = tid + r * 256;                                                    \
            int row = f >> 5, colq = f & 31;                                          \
            rb[r] = __ldg((const float4*)(Bw + (size_t)(k0 + row) * Nn + n0 + colq * 4)); \
        }                                                                             \
    }

#define S_STORE(buf, t)                                                               \
    {                                                                                 \
        int k0 = (t) * BK;                                                            \
        _Pragma("unroll") for (int r = 0; r < 2; r++) {                               \
            int f = tid + r * 256;                                                    \
            int row = f >> 2, colq = f & 3;                                           \
            float vx = ra[r].x, vy = ra[r].y, vz = ra[r].z, vw = ra[r].w;             \
            if (TRANSA) {                                                             \
                int gk = k0 + colq * 4;                                               \
                vx = fmaxf(0.f, fmaf(vx, s_sc[gk + 0], s_sh[gk + 0]));                \
                vy = fmaxf(0.f, fmaf(vy, s_sc[gk + 1], s_sh[gk + 1]));                \
                vz = fmaxf(0.f, fmaf(vz, s_sc[gk + 2], s_sh[gk + 2]));                \
                vw = fmaxf(0.f, fmaf(vw, s_sc[gk + 3], s_sh[gk + 3]));                \
            }                                                                         \
            uint4 p = make_uint4(f2tf32(vx), f2tf32(vy), f2tf32(vz), f2tf32(vw));     \
            *(uint4*)&As[buf][row][colq * 4] = p;                                     \
        }                                                                             \
        _Pragma("unroll") for (int r = 0; r < 2; r++) {                               \
            int f = tid + r * 256;                                                    \
            int row = f >> 5, colq = f & 31;                                          \
            uint4 p = make_uint4(f2tf32(rb[r].x), f2tf32(rb[r].y), f2tf32(rb[r].z),   \
                                 f2tf32(rb[r].w));                                    \
            *(uint4*)&Bs[buf][row][colq * 4] = p;                                     \
        }                                                                             \
    }

    G_LOAD(0)
    S_STORE(0, 0)
    __syncthreads();

    for (int t = 0; t < T; t++) {
        int cur = t & 1;
        if (t + 1 < T) G_LOAD(t + 1)
#pragma unroll
        for (int ks = 0; ks < 2; ks++) {
            int k0 = ks * 8;
            unsigned afr[2][4], bfr[8][2];
            int arow = warp_m + (lane >> 2);
            int akc = k0 + (lane & 3);
#pragma unroll
            for (int mf = 0; mf < 2; mf++) {
                int r = arow + mf * 16;
                afr[mf][0] = As[cur][r][akc];
                afr[mf][1] = As[cur][r + 8][akc];
                afr[mf][2] = As[cur][r][akc + 4];
                afr[mf][3] = As[cur][r + 8][akc + 4];
            }
            int bcol = warp_n + (lane >> 2);
            int bkr = k0 + (lane & 3);
#pragma unroll
            for (int nf = 0; nf < 8; nf++) {
                bfr[nf][0] = Bs[cur][bkr][bcol + nf * 8];
                bfr[nf][1] = Bs[cur][bkr + 4][bcol + nf * 8];
            }
#pragma unroll
            for (int mf = 0; mf < 2; mf++)
#pragma unroll
                for (int nf = 0; nf < 8; nf++) mma_tf32(acc[mf][nf], afr[mf], bfr[nf]);
        }
        if (t + 1 < T) {
            S_STORE((t + 1) & 1, t + 1)
            __syncthreads();
        }
    }

    // epilogue
#pragma unroll
    for (int mf = 0; mf < 2; mf++) {
        int r0 = m0 + warp_m + mf * 16 + (lane >> 2);
#pragma unroll
        for (int half = 0; half < 2; half++) {
            int gr = r0 + half * 8;
            if (gr >= M) continue;
            float sv = 1.0f;
            if (SROWBIAS) sv = __ldg(srow + gr);
#pragma unroll
            for (int nf = 0; nf < 8; nf++) {
                int gc = n0 + warp_n + nf * 8 + 2 * (lane & 3);
                float v0 = acc[mf][nf][half * 2 + 0] + sv * __ldg(bias + gc);
                float v1 = acc[mf][nf][half * 2 + 1] + sv * __ldg(bias + gc + 1);
                if (OUTH) {
                    __half2 hv = __floats2half2_rn(v0, v1);
                    *(unsigned*)((__half*)Cout + (size_t)gr * Nn + gc) = *(unsigned*)&hv;
                } else {
                    *(float2*)((float*)Cout + (size_t)gr * Nn + gc) = make_float2(v0, v1);
                }
            }
        }
    }
#undef G_LOAD
#undef S_STORE
}

// ---------------- fused head: gather(BN2+relu) -> GEMM(P1,relu) -> dot(P2) ----------------
__global__ void __launch_bounds__(256) head_fused(
    const int* __restrict__ uidx, const int* __restrict__ iidx, int n_users, int B,
    const float* __restrict__ P1, const float* __restrict__ pb1,
    const float* __restrict__ P2, const float* __restrict__ pb2,
    float* __restrict__ out) {
    const int BK = 16, T = 256 / BK;
    __shared__ unsigned As[2][128][BK + 4];
    __shared__ unsigned Bs[2][BK][128 + 8];
    __shared__ float s_sc[H2], s_sh[H2], s_pb1[H2], s_p2[H2], s_hs[128];

    int tid = threadIdx.x;
    int lane = tid & 31;
    int w = tid >> 5;
    int m0 = blockIdx.x * 128;
    int warp_m = (w & 3) * 32;
    int warp_n = (w >> 2) * 64;

    if (tid < H2) {
        s_sc[tid] = g_scale2[tid];
        s_sh[tid] = g_shift2[tid];
        s_pb1[tid] = __ldg(pb1 + tid);
        s_p2[tid] = __ldg(P2 + tid);
    }
    if (tid < 128) s_hs[tid] = 0.f;
    __syncthreads();

    int arow = tid >> 1;
    int acol = (tid & 1) * 8;
    int gb = m0 + arow;
    bool brow_ok = gb < B;
    int node_u = brow_ok ? __ldg(uidx + gb) : 0;
    int node_i = brow_ok ? (n_users + __ldg(iidx + gb)) : 0;

    float acc[2][8][4];
#pragma unroll
    for (int mf = 0; mf < 2; mf++)
#pragma unroll
        for (int nf = 0; nf < 8; nf++)
#pragma unroll
            for (int c = 0; c < 4; c++) acc[mf][nf][c] = 0.f;

    float4 ra[2], rb[2];

#define HG_LOAD(t)                                                                    \
    {                                                                                 \
        int gk = (t) * BK + acol;                                                     \
        int nd = (gk < 128) ? node_u : node_i;                                        \
        int c = gk & 127;                                                             \
        ra[0] = make_float4(0.f, 0.f, 0.f, 0.f);                                      \
        ra[1] = make_float4(0.f, 0.f, 0.f, 0.f);                                      \
        if (brow_ok) {                                                                \
            ra[0] = __ldg((const float4*)(g_y2 + (size_t)nd * H2 + c));               \
            ra[1] = __ldg((const float4*)(g_y2 + (size_t)nd * H2 + c + 4));           \
        }                                                                             \
        _Pragma("unroll") for (int r = 0; r < 2; r++) {                               \
            int f = tid + r * 256;                                                    \
            int row = f >> 5, colq = f & 31;                                          \
            rb[r] = __ldg((const float4*)(P1 + (size_t)((t) * BK + row) * H2 + colq * 4)); \
        }                                                                             \
    }

#define HS_STORE(buf, t)                                                              \
    {                                                                                 \
        int gk = (t) * BK + acol;                                                     \
        int c = gk & 127;                                                             \
        _Pragma("unroll") for (int h = 0; h < 2; h++) {                               \
            float4 v = ra[h];                                                         \
            int cc = c + h * 4;                                                       \
            v.x = fmaxf(0.f, fmaf(v.x, s_sc[cc + 0], s_sh[cc + 0]));                  \
            v.y = fmaxf(0.f, fmaf(v.y, s_sc[cc + 1], s_sh[cc + 1]));                  \
            v.z = fmaxf(0.f, fmaf(v.z, s_sc[cc + 2], s_sh[cc + 2]));                  \
            v.w = fmaxf(0.f, fmaf(v.w, s_sc[cc + 3], s_sh[cc + 3]));                  \
            uint4 p = make_uint4(f2tf32(v.x), f2tf32(v.y), f2tf32(v.z), f2tf32(v.w)); \
            *(uint4*)&As[buf][arow][acol + h * 4] = p;                                \
        }                                                                             \
        _Pragma("unroll") for (int r = 0; r < 2; r++) {                               \
            int f = tid + r * 256;                                                    \
            int row = f >> 5, colq = f & 31;                                          \
            uint4 p = make_uint4(f2tf32(rb[r].x), f2tf32(rb[r].y), f2tf32(rb[r].z),   \
                                 f2tf32(rb[r].w));                                    \
            *(uint4*)&Bs[buf][row][colq * 4] = p;                                     \
        }                                                                             \
    }

    HG_LOAD(0)
    HS_STORE(0, 0)
    __syncthreads();

    for (int t = 0; t < T; t++) {
        int cur = t & 1;
        if (t + 1 < T) HG_LOAD(t + 1)
#pragma unroll
        for (int ks = 0; ks < 2; ks++) {
            int k0 = ks * 8;
            unsigned afr[2][4], bfr[8][2];
            int arw = warp_m + (lane >> 2);
            int akc = k0 + (lane & 3);
#pragma unroll
            for (int mf = 0; mf < 2; mf++) {
                int r = arw + mf * 16;
                afr[mf][0] = As[cur][r][akc];
                afr[mf][1] = As[cur][r + 8][akc];
                afr[mf][2] = As[cur][r][akc + 4];
                afr[mf][3] = As[cur][r + 8][akc + 4];
            }
            int bc = warp_n + (lane >> 2);
            int bkr = k0 + (lane & 3);
#pragma unroll
            for (int nf = 0; nf < 8; nf++) {
                bfr[nf][0] = Bs[cur][bkr][bc + nf * 8];
                bfr[nf][1] = Bs[cur][bkr + 4][bc + nf * 8];
            }
#pragma unroll
            for (int mf = 0; mf < 2; mf++)
#pragma unroll
                for (int nf = 0; nf < 8; nf++) mma_tf32(acc[mf][nf], afr[mf], bfr[nf]);
        }
        if (t + 1 < T) {
            HS_STORE((t + 1) & 1, t + 1)
            __syncthreads();
        }
    }

#pragma unroll
    for (int mf = 0; mf < 2; mf++) {
#pragma unroll
        for (int half = 0; half < 2; half++) {
            int lr = warp_m + mf * 16 + half * 8 + (lane >> 2);
            float part = 0.f;
#pragma unroll
            for (int nf = 0; nf < 8; nf++) {
                int gc = warp_n + nf * 8 + 2 * (lane & 3);
                float v0 = fmaxf(acc[mf][nf][half * 2 + 0] + s_pb1[gc], 0.f);
                float v1 = fmaxf(acc[mf][nf][half * 2 + 1] + s_pb1[gc + 1], 0.f);
                part = fmaf(v0, s_p2[gc], part);
                part = fmaf(v1, s_p2[gc + 1], part);
            }
            atomicAdd(&s_hs[lr], part);
        }
    }
    __syncthreads();
    if (tid < 128 && m0 + tid < B) out[m0 + tid] = s_hs[tid] + __ldg(pb2);
#undef HG_LOAD
#undef HS_STORE
}

// ---------------- launch ----------------
extern "C" void kernel_launch(void* const* d_in, const int* in_sizes, int n_in,
                              void* d_out, int out_size) {
    const int* uidx = (const int*)d_in[0];
    const int* iidx = (const int*)d_in[1];
    const int* erow = (const int*)d_in[2];
    const int* ecol = (const int*)d_in[3];
    const float* eval = (const float*)d_in[4];
    const float* uemb = (const float*)d_in[5];
    const float* iemb = (const float*)d_in[6];
    const float* W1 = (const float*)d_in[7];
    const float* b1 = (const float*)d_in[8];
    const float* g1 = (const float*)d_in[9];
    const float* beta1 = (const float*)d_in[10];
    const float* W2 = (const float*)d_in[11];
    const float* b2 = (const float*)d_in[12];
    const float* g2 = (const float*)d_in[13];
    const float* beta2 = (const float*)d_in[14];
    const float* P1 = (const float*)d_in[15];
    const float* pb1 = (const float*)d_in[16];
    const float* P2 = (const float*)d_in[17];
    const float* pb2 = (const float*)d_in[18];
    float* out = (float*)d_out;

    int B = in_sizes[0];
    int E = in_sizes[2];
    int n_users = in_sizes[5] / D_IN;
    int n_items = in_sizes[6] / D_IN;
    int N = n_users + n_items;

    void *y1hp, *agg1hp, *t2hp, *sp;
    void *sum1p, *sq1p, *scale1p, *shift1p, *sum2p, *sq2p, *scale2p, *shift2p;
    void *cntp;
    cudaGetSymbolAddress(&y1hp, g_y1h);
    cudaGetSymbolAddress(&agg1hp, g_agg1h);
    cudaGetSymbolAddress(&t2hp, g_t2h);
    cudaGetSymbolAddress(&sp, g_s);
    cudaGetSymbolAddress(&sum1p, g_sum1);
    cudaGetSymbolAddress(&sq1p, g_sq1);
    cudaGetSymbolAddress(&scale1p, g_scale1);
    cudaGetSymbolAddress(&shift1p, g_shift1);
    cudaGetSymbolAddress(&sum2p, g_sum2);
    cudaGetSymbolAddress(&sq2p, g_sq2);
    cudaGetSymbolAddress(&scale2p, g_scale2);
    cudaGetSymbolAddress(&shift2p, g_shift2);
    cudaGetSymbolAddress(&cntp, g_cnt);

    cudaMemsetAsync(cntp, 0, (size_t)N * sizeof(int));
    cudaMemsetAsync(sum1p, 0, H1 * sizeof(float));
    cudaMemsetAsync(sq1p, 0, H1 * sizeof(float));
    cudaMemsetAsync(sum2p, 0, H2 * sizeof(float));
    cudaMemsetAsync(sq2p, 0, H2 * sizeof(float));

    // ----- CSR build + fp16 embedding table -----
    count_edges<<<cdiv(E, 256), 256>>>(erow, E);
    conv_emb<<<cdiv(N * 32, 256), 256>>>(uemb, iemb, n_users, N);
    scan_offsets<<<1, 1024>>>(N);
    fill_csr<<<cdiv(E, 256), 256>>>(erow, ecol, eval, E);

    // ----- Layer 1: aggregate (fp16) then transform to h1=256 (fp16 in/out) -----
    agg_emb<<<cdiv(N, 8), 256>>>(N);
    gemm_tc<true, false, true, true><<<dim3(cdiv(N, 128), H1 / 128), 256>>>(
        y1hp, W1, agg1hp, N, H1, D_IN, b1, (const float*)sp, nullptr, nullptr);
    colstats_h8<<<1024, 256>>>((const __half*)agg1hp, N, H1, (float*)sum1p, (float*)sq1p);
    bn_fin<<<1, 256>>>((const float*)sum1p, (const float*)sq1p, g1, beta1, 1.0f / N, H1,
                       (float*)scale1p, (float*)shift1p);

    // ----- Layer 2: transform (256->128, fp16 in/out) then aggregate (+stats) -----
    gemm_tc<true, true, false, true><<<dim3(cdiv(N, 128), H2 / 128), 256>>>(
        agg1hp, W2, t2hp, N, H2, H1, b2, nullptr, (const float*)scale1p,
        (const float*)shift1p);
    agg_dense_stats<<<cdiv(N, 8), 256>>>(N);
    bn_fin<<<1, 256>>>((const float*)sum2p, (const float*)sq2p, g2, beta2, 1.0f / N, H2,
                       (float*)scale2p, (float*)shift2p);

    // ----- Prediction head (fully fused) -----
    head_fused<<<cdiv(B, 128), 256>>>(uidx, iidx, n_users, B, P1, pb1, P2, pb2, out);
}

// round 17
// speedup vs baseline: 1.6742x; 1.6729x over previous
#include <cuda_runtime.h>
#include <cuda_fp16.h>
#include <math.h>
#include <stdint.h>

#define D_IN 128
#define H1 256
#define H2 128
#define NMAX 150016
#define BMAX 16384
#define EMAX 4800000

// ---------------- scratch (device globals; no runtime alloc) ----------------
__device__ __half g_y1h[(size_t)NMAX * D_IN];    // fp16 A@x
__device__ __half g_agg1h[(size_t)NMAX * H1];    // fp16 (A@x)@W1 + s b1
__device__ __half g_embh[(size_t)NMAX * D_IN];   // fp16 copy of [uemb;iemb]
__device__ __half g_t2h[(size_t)NMAX * H2];      // fp16 t2 (written by gemm2)
__device__ float g_y2[(size_t)NMAX * H2];
__device__ float g_s[NMAX];
__device__ float g_sum1[H1], g_sq1[H1], g_scale1[H1], g_shift1[H1];
__device__ float g_sum2[H2], g_sq2[H2], g_scale2[H2], g_shift2[H2];
__device__ int g_cnt[NMAX];
__device__ int g_offs[NMAX + 1];
__device__ int g_offs_tmp[NMAX];
__device__ int2 g_csr[EMAX];

static inline int cdiv(int a, int b) { return (a + b - 1) / b; }

// ---------------- numeric helpers ----------------
__device__ __forceinline__ unsigned f2tf32(float x) {
    unsigned r;
    asm("cvt.rna.tf32.f32 %0, %1;" : "=r"(r) : "f"(x));
    return r;
}
__device__ __forceinline__ void mma_tf32(float* c, const unsigned* a, const unsigned* b) {
    asm volatile(
        "mma.sync.aligned.m16n8k8.row.col.f32.tf32.tf32.f32 "
        "{%0,%1,%2,%3}, {%4,%5,%6,%7}, {%8,%9}, {%0,%1,%2,%3};"
        : "+f"(c[0]), "+f"(c[1]), "+f"(c[2]), "+f"(c[3])
        : "r"(a[0]), "r"(a[1]), "r"(a[2]), "r"(a[3]), "r"(b[0]), "r"(b[1]));
}

// ---------------- CSR build ----------------
__global__ void count_edges(const int* __restrict__ rows, int E) {
    int i = blockIdx.x * blockDim.x + threadIdx.x;
    if (i < E) atomicAdd(&g_cnt[__ldg(rows + i)], 1);
}

__global__ void __launch_bounds__(1024) scan_offsets(int N) {
    __shared__ int sums[1024];
    int t = threadIdx.x;
    int chunk = (N + 1023) / 1024;
    int lo = t * chunk;
    int hi = min(lo + chunk, N);
    int s = 0;
    for (int i = lo; i < hi; i++) s += g_cnt[i];
    sums[t] = s;
    __syncthreads();
    for (int off = 1; off < 1024; off <<= 1) {
        int add = (t >= off) ? sums[t - off] : 0;
        int v = sums[t];
        __syncthreads();
        sums[t] = v + add;
        __syncthreads();
    }
    int run = (t == 0) ? 0 : sums[t - 1];
    for (int i = lo; i < hi; i++) {
        g_offs[i] = run;
        g_offs_tmp[i] = run;
        run += g_cnt[i];
    }
    if (t == 1023) g_offs[N] = sums[1023];
}

// 2 independent edges per thread: overlaps the two returning-atomic latencies
__global__ void fill_csr2(const int* __restrict__ rows, const int* __restrict__ cols,
                          const float* __restrict__ vals, int E) {
    int half = (E + 1) >> 1;
    int i = blockIdx.x * blockDim.x + threadIdx.x;
    if (i >= half) return;
    int j = i + half;
    bool okj = (j < E);
    int r0 = __ldg(rows + i);
    int c0 = __ldg(cols + i);
    float v0 = __ldg(vals + i);
    int r1 = okj ? __ldg(rows + j) : 0;
    int c1 = okj ? __ldg(cols + j) : 0;
    float v1 = okj ? __ldg(vals + j) : 0.f;
    int p0 = atomicAdd(&g_offs_tmp[r0], 1);
    int p1 = okj ? atomicAdd(&g_offs_tmp[r1], 1) : 0;
    g_csr[p0] = make_int2(c0, __float_as_int(v0));
    if (okj) g_csr[p1] = make_int2(c1, __float_as_int(v1));
}

// ---------------- embedding -> fp16 table ----------------
__global__ void conv_emb(const float* __restrict__ uemb, const float* __restrict__ iemb,
                         int n_users, int N) {
    long long i = (long long)blockIdx.x * blockDim.x + threadIdx.x;
    long long total = (long long)N * (D_IN / 4);
    if (i >= total) return;
    int node = (int)(i >> 5);
    int q = (int)(i & 31);
    const float* src = (node < n_users) ? (uemb + (size_t)node * D_IN)
                                        : (iemb + (size_t)(node - n_users) * D_IN);
    float4 v = __ldg((const float4*)src + q);
    __half2 h0 = __floats2half2_rn(v.x, v.y);
    __half2 h1 = __floats2half2_rn(v.z, v.w);
    *(uint2*)(g_embh + (size_t)node * D_IN + q * 4) =
        make_uint2(*(unsigned*)&h0, *(unsigned*)&h1);
}

// ---------------- layer-1 aggregation (fp16 gather, fp32 accumulate, fp16 out) ----------------
__global__ void agg_emb(int N) {
    int row = (blockIdx.x * blockDim.x + threadIdx.x) >> 5;
    int lane = threadIdx.x & 31;
    if (row >= N) return;
    int start = g_offs[row];
    int end = g_offs[row + 1];
    float4 acc = make_float4(0.f, 0.f, 0.f, 0.f);
    float sv = 0.f;
#pragma unroll 4
    for (int i = start; i < end; i++) {
        int2 cv = __ldg(&g_csr[i]);
        float v = __int_as_float(cv.y);
        uint2 h = __ldg(((const uint2*)(g_embh + (size_t)cv.x * D_IN)) + lane);
        float2 f0 = __half22float2(*(__half2*)&h.x);
        float2 f1 = __half22float2(*(__half2*)&h.y);
        acc.x = fmaf(v, f0.x, acc.x);
        acc.y = fmaf(v, f0.y, acc.y);
        acc.z = fmaf(v, f1.x, acc.z);
        acc.w = fmaf(v, f1.y, acc.w);
        sv += v;
    }
    __half2 o0 = __floats2half2_rn(acc.x, acc.y);
    __half2 o1 = __floats2half2_rn(acc.z, acc.w);
    *(uint2*)(g_y1h + (size_t)row * D_IN + lane * 4) =
        make_uint2(*(unsigned*)&o0, *(unsigned*)&o1);
    if (lane == 0) g_s[row] = sv;
}

// ---------------- layer-2 aggregation (fp16 gather) + fused column stats ----------------
__global__ void agg_dense_stats(int N) {
    __shared__ float s_sum[H2], s_sq[H2];
    int tid = threadIdx.x;
    if (tid < H2) {
        s_sum[tid] = 0.f;
        s_sq[tid] = 0.f;
    }
    __syncthreads();

    int row = (blockIdx.x * blockDim.x + tid) >> 5;
    int lane = tid & 31;
    if (row < N) {
        int start = g_offs[row];
        int end = g_offs[row + 1];
        float4 acc = make_float4(0.f, 0.f, 0.f, 0.f);
#pragma unroll 4
        for (int i = start; i < end; i++) {
            int2 cv = __ldg(&g_csr[i]);
            float v = __int_as_float(cv.y);
            uint2 h = __ldg(((const uint2*)(g_t2h + (size_t)cv.x * H2)) + lane);
            float2 f0 = __half22float2(*(__half2*)&h.x);
            float2 f1 = __half22float2(*(__half2*)&h.y);
            acc.x = fmaf(v, f0.x, acc.x);
            acc.y = fmaf(v, f0.y, acc.y);
            acc.z = fmaf(v, f1.x, acc.z);
            acc.w = fmaf(v, f1.y, acc.w);
        }
        *(float4*)(g_y2 + (size_t)row * H2 + lane * 4) = acc;
        atomicAdd(&s_sum[lane * 4 + 0], acc.x);
        atomicAdd(&s_sum[lane * 4 + 1], acc.y);
        atomicAdd(&s_sum[lane * 4 + 2], acc.z);
        atomicAdd(&s_sum[lane * 4 + 3], acc.w);
        atomicAdd(&s_sq[lane * 4 + 0], acc.x * acc.x);
        atomicAdd(&s_sq[lane * 4 + 1], acc.y * acc.y);
        atomicAdd(&s_sq[lane * 4 + 2], acc.z * acc.z);
        atomicAdd(&s_sq[lane * 4 + 3], acc.w * acc.w);
    }
    __syncthreads();
    if (tid < H2) {
        atomicAdd(&g_sum2[tid], s_sum[tid]);
        atomicAdd(&g_sq2[tid], s_sq[tid]);
    }
}

// ---------------- layer-1 column stats: uint4 loads, smem block-reduce, 1 atomic/col/block ----------------
__global__ void colstats_h8s(const __half* __restrict__ X, int M, int C,
                             float* __restrict__ osum, float* __restrict__ osq) {
    __shared__ float shs[8][256];
    __shared__ float shq[8][256];
    int tid = threadIdx.x;
    int cg = tid & 31;    // 32 col-groups of 8 (C=256)
    int sub = tid >> 5;   // 8 row stripes
    float s[8] = {}, q[8] = {};
    for (int r = blockIdx.x * 8 + sub; r < M; r += gridDim.x * 8) {
        uint4 hv = __ldg((const uint4*)(X + (size_t)r * C + cg * 8));
        const unsigned* hw = &hv.x;
#pragma unroll
        for (int j = 0; j < 4; j++) {
            float2 f = __half22float2(*(__half2*)&hw[j]);
            s[2 * j] += f.x;
            q[2 * j] += f.x * f.x;
            s[2 * j + 1] += f.y;
            q[2 * j + 1] += f.y * f.y;
        }
    }
#pragma unroll
    for (int j = 0; j < 8; j++) {
        shs[sub][cg * 8 + j] = s[j];
        shq[sub][cg * 8 + j] = q[j];
    }
    __syncthreads();
    // tid == column index (blockDim.x == 256 == C)
    float ts = 0.f, tq = 0.f;
#pragma unroll
    for (int k = 0; k < 8; k++) {
        ts += shs[k][tid];
        tq += shq[k][tid];
    }
    atomicAdd(&osum[tid], ts);
    atomicAdd(&osq[tid], tq);
}

__global__ void bn_fin(const float* __restrict__ isum, const float* __restrict__ isq,
                       const float* __restrict__ g, const float* __restrict__ beta,
                       float invM, int C, float* __restrict__ oscale, float* __restrict__ oshift) {
    int c = threadIdx.x;
    if (c < C) {
        float mu = isum[c] * invM;
        float var = isq[c] * invM - mu * mu;
        float rs = rsqrtf(var + 1e-5f);
        float sc = rs * g[c];
        oscale[c] = sc;
        oshift[c] = beta[c] - mu * sc;
    }
}

// ---------------- TF32 tensor-core GEMM: 128x128x16 CTA, 8 warps (32x64 each) ----------------
// INH: A is fp16.  OUTH: write fp16 C.
template <bool INH, bool TRANSA, bool SROWBIAS, bool OUTH>
__global__ void __launch_bounds__(256) gemm_tc(
    const void* __restrict__ A, const float* __restrict__ Bw, void* __restrict__ Cout,
    int M, int Nn, int Kk,
    const float* __restrict__ bias, const float* __restrict__ srow,
    const float* __restrict__ tscale, const float* __restrict__ tshift) {
    const int BM = 128, BN = 128, BK = 16;
    __shared__ unsigned As[2][BM][BK + 4];   // [m][k]
    __shared__ unsigned Bs[2][BK][BN + 4];   // [k][n]
    __shared__ float s_sc[256], s_sh[256];

    int tid = threadIdx.x;
    int lane = tid & 31;
    int w = tid >> 5;
    int m0 = blockIdx.x * BM;
    int n0 = blockIdx.y * BN;
    int warp_m = (w & 3) * 32;
    int warp_n = (w >> 2) * 64;

    if (TRANSA) {
        for (int k = tid; k < Kk; k += 256) {
            s_sc[k] = tscale[k];
            s_sh[k] = tshift[k];
        }
        __syncthreads();
    }

    float acc[2][8][4];
#pragma unroll
    for (int mf = 0; mf < 2; mf++)
#pragma unroll
        for (int nf = 0; nf < 8; nf++)
#pragma unroll
            for (int c = 0; c < 4; c++) acc[mf][nf][c] = 0.f;

    int T = Kk / BK;
    float4 ra[2], rb[2];

#define G_LOAD(t)                                                                     \
    {                                                                                 \
        int k0 = (t) * BK;                                                            \
        _Pragma("unroll") for (int r = 0; r < 2; r++) {                               \
            int f = tid + r * 256;                                                    \
            int row = f >> 2, colq = f & 3;                                           \
            ra[r] = make_float4(0.f, 0.f, 0.f, 0.f);                                  \
            if (m0 + row < M) {                                                       \
                if (INH) {                                                            \
                    uint2 hv = __ldg((const uint2*)((const __half*)A +                \
                                     (size_t)(m0 + row) * Kk + k0 + colq * 4));       \
                    float2 a0 = __half22float2(*(__half2*)&hv.x);                     \
                    float2 a1 = __half22float2(*(__half2*)&hv.y);                     \
                    ra[r] = make_float4(a0.x, a0.y, a1.x, a1.y);                      \
                } else {                                                              \
                    ra[r] = __ldg((const float4*)((const float*)A +                   \
                                  (size_t)(m0 + row) * Kk + k0 + colq * 4));          \
                }                                                                     \
            }                                                                         \
        }                                                                             \
        _Pragma("unroll") for (int r = 0; r < 2; r++) {                               \
            int f = tid + r * 256;                                                    \
            int row = f >> 5, colq = f & 31;                                          \
            rb[r] = __ldg((const float4*)(Bw + (size_t)(k0 + row) * Nn + n0 + colq * 4)); \
        }                                                                             \
    }

#define S_STORE(buf, t)                                                               \
    {                                                                                 \
        int k0 = (t) * BK;                                                            \
        _Pragma("unroll") for (int r = 0; r < 2; r++) {                               \
            int f = tid + r * 256;                                                    \
            int row = f >> 2, colq = f & 3;                                           \
            float vx = ra[r].x, vy = ra[r].y, vz = ra[r].z, vw = ra[r].w;             \
            if (TRANSA) {                                                             \
                int gk = k0 + colq * 4;                                               \
                vx = fmaxf(0.f, fmaf(vx, s_sc[gk + 0], s_sh[gk + 0]));                \
                vy = fmaxf(0.f, fmaf(vy, s_sc[gk + 1], s_sh[gk + 1]));                \
                vz = fmaxf(0.f, fmaf(vz, s_sc[gk + 2], s_sh[gk + 2]));                \
                vw = fmaxf(0.f, fmaf(vw, s_sc[gk + 3], s_sh[gk + 3]));                \
            }                                                                         \
            uint4 p = make_uint4(f2tf32(vx), f2tf32(vy), f2tf32(vz), f2tf32(vw));     \
            *(uint4*)&As[buf][row][colq * 4] = p;                                     \
        }                                                                             \
        _Pragma("unroll") for (int r = 0; r < 2; r++) {                               \
            int f = tid + r * 256;                                                    \
            int row = f >> 5, colq = f & 31;                                          \
            uint4 p = make_uint4(f2tf32(rb[r].x), f2tf32(rb[r].y), f2tf32(rb[r].z),   \
                                 f2tf32(rb[r].w));                                    \
            *(uint4*)&Bs[buf][row][colq * 4] = p;                                     \
        }                                                                             \
    }

    G_LOAD(0)
    S_STORE(0, 0)
    __syncthreads();

    for (int t = 0; t < T; t++) {
        int cur = t & 1;
        if (t + 1 < T) G_LOAD(t + 1)
#pragma unroll
        for (int ks = 0; ks < 2; ks++) {
            int k0 = ks * 8;
            unsigned afr[2][4], bfr[8][2];
            int arow = warp_m + (lane >> 2);
            int akc = k0 + (lane & 3);
#pragma unroll
            for (int mf = 0; mf < 2; mf++) {
                int r = arow + mf * 16;
                afr[mf][0] = As[cur][r][akc];
                afr[mf][1] = As[cur][r + 8][akc];
                afr[mf][2] = As[cur][r][akc + 4];
                afr[mf][3] = As[cur][r + 8][akc + 4];
            }
            int bcol = warp_n + (lane >> 2);
            int bkr = k0 + (lane & 3);
#pragma unroll
            for (int nf = 0; nf < 8; nf++) {
                bfr[nf][0] = Bs[cur][bkr][bcol + nf * 8];
                bfr[nf][1] = Bs[cur][bkr + 4][bcol + nf * 8];
            }
#pragma unroll
            for (int mf = 0; mf < 2; mf++)
#pragma unroll
                for (int nf = 0; nf < 8; nf++) mma_tf32(acc[mf][nf], afr[mf], bfr[nf]);
        }
        if (t + 1 < T) {
            S_STORE((t + 1) & 1, t + 1)
            __syncthreads();
        }
    }

    // epilogue
#pragma unroll
    for (int mf = 0; mf < 2; mf++) {
        int r0 = m0 + warp_m + mf * 16 + (lane >> 2);
#pragma unroll
        for (int half = 0; half < 2; half++) {
            int gr = r0 + half * 8;
            if (gr >= M) continue;
            float sv = 1.0f;
            if (SROWBIAS) sv = __ldg(srow + gr);
#pragma unroll
            for (int nf = 0; nf < 8; nf++) {
                int gc = n0 + warp_n + nf * 8 + 2 * (lane & 3);
                float v0 = acc[mf][nf][half * 2 + 0] + sv * __ldg(bias + gc);
                float v1 = acc[mf][nf][half * 2 + 1] + sv * __ldg(bias + gc + 1);
                if (OUTH) {
                    __half2 hv = __floats2half2_rn(v0, v1);
                    *(unsigned*)((__half*)Cout + (size_t)gr * Nn + gc) = *(unsigned*)&hv;
                } else {
                    *(float2*)((float*)Cout + (size_t)gr * Nn + gc) = make_float2(v0, v1);
                }
            }
        }
    }
#undef G_LOAD
#undef S_STORE
}

// ---------------- fused head: gather(BN2+relu) -> GEMM(P1,relu) -> dot(P2) ----------------
__global__ void __launch_bounds__(256) head_fused(
    const int* __restrict__ uidx, const int* __restrict__ iidx, int n_users, int B,
    const float* __restrict__ P1, const float* __restrict__ pb1,
    const float* __restrict__ P2, const float* __restrict__ pb2,
    float* __restrict__ out) {
    const int BK = 16, T = 256 / BK;
    __shared__ unsigned As[2][128][BK + 4];
    __shared__ unsigned Bs[2][BK][128 + 8];
    __shared__ float s_sc[H2], s_sh[H2], s_pb1[H2], s_p2[H2], s_hs[128];

    int tid = threadIdx.x;
    int lane = tid & 31;
    int w = tid >> 5;
    int m0 = blockIdx.x * 128;
    int warp_m = (w & 3) * 32;
    int warp_n = (w >> 2) * 64;

    if (tid < H2) {
        s_sc[tid] = g_scale2[tid];
        s_sh[tid] = g_shift2[tid];
        s_pb1[tid] = __ldg(pb1 + tid);
        s_p2[tid] = __ldg(P2 + tid);
    }
    if (tid < 128) s_hs[tid] = 0.f;
    __syncthreads();

    int arow = tid >> 1;
    int acol = (tid & 1) * 8;
    int gb = m0 + arow;
    bool brow_ok = gb < B;
    int node_u = brow_ok ? __ldg(uidx + gb) : 0;
    int node_i = brow_ok ? (n_users + __ldg(iidx + gb)) : 0;

    float acc[2][8][4];
#pragma unroll
    for (int mf = 0; mf < 2; mf++)
#pragma unroll
        for (int nf = 0; nf < 8; nf++)
#pragma unroll
            for (int c = 0; c < 4; c++) acc[mf][nf][c] = 0.f;

    float4 ra[2], rb[2];

#define HG_LOAD(t)                                                                    \
    {                                                                                 \
        int gk = (t) * BK + acol;                                                     \
        int nd = (gk < 128) ? node_u : node_i;                                        \
        int c = gk & 127;                                                             \
        ra[0] = make_float4(0.f, 0.f, 0.f, 0.f);                                      \
        ra[1] = make_float4(0.f, 0.f, 0.f, 0.f);                                      \
        if (brow_ok) {                                                                \
            ra[0] = __ldg((const float4*)(g_y2 + (size_t)nd * H2 + c));               \
            ra[1] = __ldg((const float4*)(g_y2 + (size_t)nd * H2 + c + 4));           \
        }                                                                             \
        _Pragma("unroll") for (int r = 0; r < 2; r++) {                               \
            int f = tid + r * 256;                                                    \
            int row = f >> 5, colq = f & 31;                                          \
            rb[r] = __ldg((const float4*)(P1 + (size_t)((t) * BK + row) * H2 + colq * 4)); \
        }                                                                             \
    }

#define HS_STORE(buf, t)                                                              \
    {                                                                                 \
        int gk = (t) * BK + acol;                                                     \
        int c = gk & 127;                                                             \
        _Pragma("unroll") for (int h = 0; h < 2; h++) {                               \
            float4 v = ra[h];                                                         \
            int cc = c + h * 4;                                                       \
            v.x = fmaxf(0.f, fmaf(v.x, s_sc[cc + 0], s_sh[cc + 0]));                  \
            v.y = fmaxf(0.f, fmaf(v.y, s_sc[cc + 1], s_sh[cc + 1]));                  \
            v.z = fmaxf(0.f, fmaf(v.z, s_sc[cc + 2], s_sh[cc + 2]));                  \
            v.w = fmaxf(0.f, fmaf(v.w, s_sc[cc + 3], s_sh[cc + 3]));                  \
            uint4 p = make_uint4(f2tf32(v.x), f2tf32(v.y), f2tf32(v.z), f2tf32(v.w)); \
            *(uint4*)&As[buf][arow][acol + h * 4] = p;                                \
        }                                                                             \
        _Pragma("unroll") for (int r = 0; r < 2; r++) {                               \
            int f = tid + r * 256;                                                    \
            int row = f >> 5, colq = f & 31;                                          \
            uint4 p = make_uint4(f2tf32(rb[r].x), f2tf32(rb[r].y), f2tf32(rb[r].z),   \
                                 f2tf32(rb[r].w));                                    \
            *(uint4*)&Bs[buf][row][colq * 4] = p;                                     \
        }                                                                             \
    }

    HG_LOAD(0)
    HS_STORE(0, 0)
    __syncthreads();

    for (int t = 0; t < T; t++) {
        int cur = t & 1;
        if (t + 1 < T) HG_LOAD(t + 1)
#pragma unroll
        for (int ks = 0; ks < 2; ks++) {
            int k0 = ks * 8;
            unsigned afr[2][4], bfr[8][2];
            int arw = warp_m + (lane >> 2);
            int akc = k0 + (lane & 3);
#pragma unroll
            for (int mf = 0; mf < 2; mf++) {
                int r = arw + mf * 16;
                afr[mf][0] = As[cur][r][akc];
                afr[mf][1] = As[cur][r + 8][akc];
                afr[mf][2] = As[cur][r][akc + 4];
                afr[mf][3] = As[cur][r + 8][akc + 4];
            }
            int bc = warp_n + (lane >> 2);
            int bkr = k0 + (lane & 3);
#pragma unroll
            for (int nf = 0; nf < 8; nf++) {
                bfr[nf][0] = Bs[cur][bkr][bc + nf * 8];
                bfr[nf][1] = Bs[cur][bkr + 4][bc + nf * 8];
            }
#pragma unroll
            for (int mf = 0; mf < 2; mf++)
#pragma unroll
                for (int nf = 0; nf < 8; nf++) mma_tf32(acc[mf][nf], afr[mf], bfr[nf]);
        }
        if (t + 1 < T) {
            HS_STORE((t + 1) & 1, t + 1)
            __syncthreads();
        }
    }

#pragma unroll
    for (int mf = 0; mf < 2; mf++) {
#pragma unroll
        for (int half = 0; half < 2; half++) {
            int lr = warp_m + mf * 16 + half * 8 + (lane >> 2);
            float part = 0.f;
#pragma unroll
            for (int nf = 0; nf < 8; nf++) {
                int gc = warp_n + nf * 8 + 2 * (lane & 3);
                float v0 = fmaxf(acc[mf][nf][half * 2 + 0] + s_pb1[gc], 0.f);
                float v1 = fmaxf(acc[mf][nf][half * 2 + 1] + s_pb1[gc + 1], 0.f);
                part = fmaf(v0, s_p2[gc], part);
                part = fmaf(v1, s_p2[gc + 1], part);
            }
            atomicAdd(&s_hs[lr], part);
        }
    }
    __syncthreads();
    if (tid < 128 && m0 + tid < B) out[m0 + tid] = s_hs[tid] + __ldg(pb2);
#undef HG_LOAD
#undef HS_STORE
}

// ---------------- launch ----------------
extern "C" void kernel_launch(void* const* d_in, const int* in_sizes, int n_in,
                              void* d_out, int out_size) {
    const int* uidx = (const int*)d_in[0];
    const int* iidx = (const int*)d_in[1];
    const int* erow = (const int*)d_in[2];
    const int* ecol = (const int*)d_in[3];
    const float* eval = (const float*)d_in[4];
    const float* uemb = (const float*)d_in[5];
    const float* iemb = (const float*)d_in[6];
    const float* W1 = (const float*)d_in[7];
    const float* b1 = (const float*)d_in[8];
    const float* g1 = (const float*)d_in[9];
    const float* beta1 = (const float*)d_in[10];
    const float* W2 = (const float*)d_in[11];
    const float* b2 = (const float*)d_in[12];
    const float* g2 = (const float*)d_in[13];
    const float* beta2 = (const float*)d_in[14];
    const float* P1 = (const float*)d_in[15];
    const float* pb1 = (const float*)d_in[16];
    const float* P2 = (const float*)d_in[17];
    const float* pb2 = (const float*)d_in[18];
    float* out = (float*)d_out;

    int B = in_sizes[0];
    int E = in_sizes[2];
    int n_users = in_sizes[5] / D_IN;
    int n_items = in_sizes[6] / D_IN;
    int N = n_users + n_items;

    void *y1hp, *agg1hp, *t2hp, *sp;
    void *sum1p, *sq1p, *scale1p, *shift1p, *sum2p, *sq2p, *scale2p, *shift2p;
    void *cntp;
    cudaGetSymbolAddress(&y1hp, g_y1h);
    cudaGetSymbolAddress(&agg1hp, g_agg1h);
    cudaGetSymbolAddress(&t2hp, g_t2h);
    cudaGetSymbolAddress(&sp, g_s);
    cudaGetSymbolAddress(&sum1p, g_sum1);
    cudaGetSymbolAddress(&sq1p, g_sq1);
    cudaGetSymbolAddress(&scale1p, g_scale1);
    cudaGetSymbolAddress(&shift1p, g_shift1);
    cudaGetSymbolAddress(&sum2p, g_sum2);
    cudaGetSymbolAddress(&sq2p, g_sq2);
    cudaGetSymbolAddress(&scale2p, g_scale2);
    cudaGetSymbolAddress(&shift2p, g_shift2);
    cudaGetSymbolAddress(&cntp, g_cnt);

    cudaMemsetAsync(cntp, 0, (size_t)N * sizeof(int));
    cudaMemsetAsync(sum1p, 0, H1 * sizeof(float));
    cudaMemsetAsync(sq1p, 0, H1 * sizeof(float));
    cudaMemsetAsync(sum2p, 0, H2 * sizeof(float));
    cudaMemsetAsync(sq2p, 0, H2 * sizeof(float));

    // ----- CSR build + fp16 embedding table -----
    count_edges<<<cdiv(E, 256), 256>>>(erow, E);
    conv_emb<<<cdiv(N * 32, 256), 256>>>(uemb, iemb, n_users, N);
    scan_offsets<<<1, 1024>>>(N);
    fill_csr2<<<cdiv((E + 1) / 2, 256), 256>>>(erow, ecol, eval, E);

    // ----- Layer 1: aggregate (fp16) then transform to h1=256 (fp16 in/out) -----
    agg_emb<<<cdiv(N, 8), 256>>>(N);
    gemm_tc<true, false, true, true><<<dim3(cdiv(N, 128), H1 / 128), 256>>>(
        y1hp, W1, agg1hp, N, H1, D_IN, b1, (const float*)sp, nullptr, nullptr);
    colstats_h8s<<<1024, 256>>>((const __half*)agg1hp, N, H1, (float*)sum1p, (float*)sq1p);
    bn_fin<<<1, 256>>>((const float*)sum1p, (const float*)sq1p, g1, beta1, 1.0f / N, H1,
                       (float*)scale1p, (float*)shift1p);

    // ----- Layer 2: transform (256->128, fp16 in/out) then aggregate (+stats) -----
    gemm_tc<true, true, false, true><<<dim3(cdiv(N, 128), H2 / 128), 256>>>(
        agg1hp, W2, t2hp, N, H2, H1, b2, nullptr, (const float*)scale1p,
        (const float*)shift1p);
    agg_dense_stats<<<cdiv(N, 8), 256>>>(N);
    bn_fin<<<1, 256>>>((const float*)sum2p, (const float*)sq2p, g2, beta2, 1.0f / N, H2,
                       (float*)scale2p, (float*)shift2p);

    // ----- Prediction head (fully fused) -----
    head_fused<<<cdiv(B, 128), 256>>>(uidx, iidx, n_users, B, P1, pb1, P2, pb2, out);
}